// round 1
// baseline (speedup 1.0000x reference)
#include <cuda_runtime.h>
#include <cstdint>
#include <math.h>

#define BATCH  16384
#define DMODEL 2048
#define RANK   64
#define NPROJ  192   // dt | phase | B concatenated

// ---------------------------------------------------------------------------
// helpers
// ---------------------------------------------------------------------------
__device__ __forceinline__ float tf32r(float v) {
    uint32_t u;
    asm("cvt.rna.tf32.f32 %0, %1;" : "=r"(u) : "f"(v));
    return __uint_as_float(u);
}

// D += A(16x8,row) * B(8x8,col)  tf32 inputs, f32 accum
__device__ __forceinline__ void mma_tf32(float* d, const float* a, const float* b) {
    const uint32_t* A = reinterpret_cast<const uint32_t*>(a);
    const uint32_t* B = reinterpret_cast<const uint32_t*>(b);
    asm volatile(
        "mma.sync.aligned.m16n8k8.row.col.f32.tf32.tf32.f32 "
        "{%0,%1,%2,%3}, {%4,%5,%6,%7}, {%8,%9}, {%0,%1,%2,%3};\n"
        : "+f"(d[0]), "+f"(d[1]), "+f"(d[2]), "+f"(d[3])
        : "r"(A[0]), "r"(A[1]), "r"(A[2]), "r"(A[3]), "r"(B[0]), "r"(B[1]));
}

// ---------------------------------------------------------------------------
// Kernel 1: P = x @ [W_dt;W_ph;W_B]^T  (M=16384, N=192, K=2048)
//           + fused elementwise state update -> new_re, new_im
// CTA: 256 thr (8 warps, 2x4), tile 64x192, BK=32. smem ld = 32+4 (pad).
// ---------------------------------------------------------------------------
#define LDK 36      // smem leading dim for K-tiles (32 + 4 pad -> conflict-free frags)
#define LDP 196     // smem leading dim for P tile  (192 + 4 pad)

__global__ void __launch_bounds__(256) proj_kernel(
    const float* __restrict__ x,
    const float* __restrict__ sre, const float* __restrict__ sim_,
    const float* __restrict__ Wdt, const float* __restrict__ bdt,
    const float* __restrict__ Wph, const float* __restrict__ bph,
    const float* __restrict__ WB,
    const float* __restrict__ Areal, const float* __restrict__ Aimag,
    float* __restrict__ nre, float* __restrict__ nim)
{
    extern __shared__ float smemf[];
    float* sA = smemf;                 // 64  x LDK
    float* sB = smemf + 64 * LDK;      // 192 x LDK

    const int tid  = threadIdx.x;
    const int wid  = tid >> 5;
    const int lane = tid & 31;
    const int g    = lane >> 2;        // 0..7
    const int t    = lane & 3;         // 0..3
    const int wm   = wid >> 2;         // 0..1  (32 rows each)
    const int wn   = wid & 3;          // 0..3  (48 cols each)
    const int m0   = blockIdx.x * 64;

    float acc[2][6][4];
    #pragma unroll
    for (int i = 0; i < 2; i++)
        #pragma unroll
        for (int j = 0; j < 6; j++)
            #pragma unroll
            for (int k = 0; k < 4; k++) acc[i][j][k] = 0.f;

    float4 ra[2], rbuf[6];

    // ---- prologue: load tile kt=0 ----
    #pragma unroll
    for (int i = 0; i < 2; i++) {
        int idx = tid + i * 256;
        int row = idx >> 3, c4 = (idx & 7) << 2;
        ra[i] = *reinterpret_cast<const float4*>(x + (size_t)(m0 + row) * DMODEL + c4);
    }
    #pragma unroll
    for (int i = 0; i < 6; i++) {
        int idx = tid + i * 256;
        int row = idx >> 3, c4 = (idx & 7) << 2;
        const float* W = (row < 64)  ? (Wdt + (size_t)row * DMODEL)
                       : (row < 128) ? (Wph + (size_t)(row - 64) * DMODEL)
                                     : (WB  + (size_t)(row - 128) * DMODEL);
        rbuf[i] = *reinterpret_cast<const float4*>(W + c4);
    }
    // store tile 0
    #pragma unroll
    for (int i = 0; i < 2; i++) {
        int idx = tid + i * 256;
        int row = idx >> 3, c4 = (idx & 7) << 2;
        float4 v = ra[i], w;
        w.x = tf32r(v.x); w.y = tf32r(v.y); w.z = tf32r(v.z); w.w = tf32r(v.w);
        *reinterpret_cast<float4*>(sA + row * LDK + c4) = w;
    }
    #pragma unroll
    for (int i = 0; i < 6; i++) {
        int idx = tid + i * 256;
        int row = idx >> 3, c4 = (idx & 7) << 2;
        float4 v = rbuf[i], w;
        w.x = tf32r(v.x); w.y = tf32r(v.y); w.z = tf32r(v.z); w.w = tf32r(v.w);
        *reinterpret_cast<float4*>(sB + row * LDK + c4) = w;
    }
    __syncthreads();

    // ---- main K loop (64 tiles of 32) ----
    for (int kt = 0; kt < DMODEL / 32; ++kt) {
        // prefetch next tile into regs while computing this one
        if (kt + 1 < DMODEL / 32) {
            int koff = (kt + 1) * 32;
            #pragma unroll
            for (int i = 0; i < 2; i++) {
                int idx = tid + i * 256;
                int row = idx >> 3, c4 = (idx & 7) << 2;
                ra[i] = *reinterpret_cast<const float4*>(
                    x + (size_t)(m0 + row) * DMODEL + koff + c4);
            }
            #pragma unroll
            for (int i = 0; i < 6; i++) {
                int idx = tid + i * 256;
                int row = idx >> 3, c4 = (idx & 7) << 2;
                const float* W = (row < 64)  ? (Wdt + (size_t)row * DMODEL)
                               : (row < 128) ? (Wph + (size_t)(row - 64) * DMODEL)
                                             : (WB  + (size_t)(row - 128) * DMODEL);
                rbuf[i] = *reinterpret_cast<const float4*>(W + koff + c4);
            }
        }

        // compute: 4 k8 steps
        #pragma unroll
        for (int k8 = 0; k8 < 4; k8++) {
            int kk = k8 * 8;
            float afr[2][4], bfr[6][2];
            #pragma unroll
            for (int nt = 0; nt < 6; nt++) {
                int nb = wn * 48 + nt * 8;
                bfr[nt][0] = sB[(nb + g) * LDK + kk + t];
                bfr[nt][1] = sB[(nb + g) * LDK + kk + t + 4];
            }
            #pragma unroll
            for (int mt = 0; mt < 2; mt++) {
                int rb0 = wm * 32 + mt * 16;
                afr[mt][0] = sA[(rb0 + g)     * LDK + kk + t];
                afr[mt][1] = sA[(rb0 + g + 8) * LDK + kk + t];
                afr[mt][2] = sA[(rb0 + g)     * LDK + kk + t + 4];
                afr[mt][3] = sA[(rb0 + g + 8) * LDK + kk + t + 4];
            }
            #pragma unroll
            for (int mt = 0; mt < 2; mt++)
                #pragma unroll
                for (int nt = 0; nt < 6; nt++)
                    mma_tf32(acc[mt][nt], afr[mt], bfr[nt]);
        }
        __syncthreads();

        if (kt + 1 < DMODEL / 32) {
            #pragma unroll
            for (int i = 0; i < 2; i++) {
                int idx = tid + i * 256;
                int row = idx >> 3, c4 = (idx & 7) << 2;
                float4 v = ra[i], w;
                w.x = tf32r(v.x); w.y = tf32r(v.y); w.z = tf32r(v.z); w.w = tf32r(v.w);
                *reinterpret_cast<float4*>(sA + row * LDK + c4) = w;
            }
            #pragma unroll
            for (int i = 0; i < 6; i++) {
                int idx = tid + i * 256;
                int row = idx >> 3, c4 = (idx & 7) << 2;
                float4 v = rbuf[i], w;
                w.x = tf32r(v.x); w.y = tf32r(v.y); w.z = tf32r(v.z); w.w = tf32r(v.w);
                *reinterpret_cast<float4*>(sB + row * LDK + c4) = w;
            }
            __syncthreads();
        }
    }

    // ---- stage P tile (64 x 192) into smem (overlaps sA/sB; safe post-sync) ----
    float* P = smemf;   // 64 x LDP
    #pragma unroll
    for (int mt = 0; mt < 2; mt++) {
        int r0 = wm * 32 + mt * 16 + g;
        #pragma unroll
        for (int nt = 0; nt < 6; nt++) {
            int c0 = wn * 48 + nt * 8 + 2 * t;
            P[r0 * LDP + c0]           = acc[mt][nt][0];
            P[r0 * LDP + c0 + 1]       = acc[mt][nt][1];
            P[(r0 + 8) * LDP + c0]     = acc[mt][nt][2];
            P[(r0 + 8) * LDP + c0 + 1] = acc[mt][nt][3];
        }
    }
    __syncthreads();

    // ---- fused elementwise state update ----
    const float PI_F = 3.14159265358979323846f;
    #pragma unroll
    for (int i = 0; i < 16; i++) {
        int idx  = tid + i * 256;          // 64 rows * 64 ranks
        int row  = idx >> 6;
        int r    = idx & 63;
        int grow = m0 + row;

        float zdt   = P[row * LDP + r] + bdt[r];
        float dt    = (zdt > 20.f) ? zdt : log1pf(expf(zdt));
        float zph   = P[row * LDP + 64 + r] + bph[r];
        float phase = tanhf(zph) * PI_F;
        float decay = expf(-dt * expf(Areal[r]));
        float angle = fmaf(dt, Aimag[r], phase);
        float Bv    = P[row * LDP + 128 + r];

        float sn, cs;
        sincosf(angle, &sn, &cs);

        float a_ = sre[(size_t)grow * RANK + r];
        float b_ = sim_[(size_t)grow * RANK + r];

        nre[(size_t)grow * RANK + r] = fmaf(a_ * cs - b_ * sn, decay, Bv);
        nim[(size_t)grow * RANK + r] = (a_ * sn + b_ * cs) * decay;
    }
}

// ---------------------------------------------------------------------------
// Kernel 2: out = new_re @ W_C^T   (M=16384, N=2048, K=64)
// CTA: 256 thr (8 warps, 2x4), tile 128x128, whole K in smem (ld = 68).
// ---------------------------------------------------------------------------
#define LDK2 68

__global__ void __launch_bounds__(256) out_kernel(
    const float* __restrict__ nre,
    const float* __restrict__ WC,
    float* __restrict__ out)
{
    extern __shared__ float smemf[];
    float* sA = smemf;                  // 128 x LDK2
    float* sB = smemf + 128 * LDK2;     // 128 x LDK2

    const int tid  = threadIdx.x;
    const int wid  = tid >> 5;
    const int lane = tid & 31;
    const int g    = lane >> 2;
    const int t    = lane & 3;
    const int wm   = wid >> 2;          // 0..1 (64 rows each)
    const int wn   = wid & 3;           // 0..3 (32 cols each)
    const int m0   = blockIdx.x * 128;
    const int n0   = blockIdx.y * 128;

    #pragma unroll
    for (int i = 0; i < 8; i++) {
        int idx = tid + i * 256;        // 128 rows * 16 float4
        int row = idx >> 4, c4 = (idx & 15) << 2;
        float4 v = *reinterpret_cast<const float4*>(nre + (size_t)(m0 + row) * RANK + c4);
        float4 w;
        w.x = tf32r(v.x); w.y = tf32r(v.y); w.z = tf32r(v.z); w.w = tf32r(v.w);
        *reinterpret_cast<float4*>(sA + row * LDK2 + c4) = w;

        v = *reinterpret_cast<const float4*>(WC + (size_t)(n0 + row) * RANK + c4);
        w.x = tf32r(v.x); w.y = tf32r(v.y); w.z = tf32r(v.z); w.w = tf32r(v.w);
        *reinterpret_cast<float4*>(sB + row * LDK2 + c4) = w;
    }
    __syncthreads();

    float acc[4][4][4];
    #pragma unroll
    for (int i = 0; i < 4; i++)
        #pragma unroll
        for (int j = 0; j < 4; j++)
            #pragma unroll
            for (int k = 0; k < 4; k++) acc[i][j][k] = 0.f;

    #pragma unroll
    for (int k8 = 0; k8 < 8; k8++) {
        int kk = k8 * 8;
        float afr[4][4], bfr[4][2];
        #pragma unroll
        for (int mt = 0; mt < 4; mt++) {
            int rb0 = wm * 64 + mt * 16;
            afr[mt][0] = sA[(rb0 + g)     * LDK2 + kk + t];
            afr[mt][1] = sA[(rb0 + g + 8) * LDK2 + kk + t];
            afr[mt][2] = sA[(rb0 + g)     * LDK2 + kk + t + 4];
            afr[mt][3] = sA[(rb0 + g + 8) * LDK2 + kk + t + 4];
        }
        #pragma unroll
        for (int nt = 0; nt < 4; nt++) {
            int nb = wn * 32 + nt * 8;
            bfr[nt][0] = sB[(nb + g) * LDK2 + kk + t];
            bfr[nt][1] = sB[(nb + g) * LDK2 + kk + t + 4];
        }
        #pragma unroll
        for (int mt = 0; mt < 4; mt++)
            #pragma unroll
            for (int nt = 0; nt < 4; nt++)
                mma_tf32(acc[mt][nt], afr[mt], bfr[nt]);
    }

    #pragma unroll
    for (int mt = 0; mt < 4; mt++) {
        int row = m0 + wm * 64 + mt * 16 + g;
        #pragma unroll
        for (int nt = 0; nt < 4; nt++) {
            int col = n0 + wn * 32 + nt * 8 + 2 * t;
            *reinterpret_cast<float2*>(out + (size_t)row * DMODEL + col) =
                make_float2(acc[mt][nt][0], acc[mt][nt][1]);
            *reinterpret_cast<float2*>(out + (size_t)(row + 8) * DMODEL + col) =
                make_float2(acc[mt][nt][2], acc[mt][nt][3]);
        }
    }
}

// ---------------------------------------------------------------------------
// launch
// ---------------------------------------------------------------------------
extern "C" void kernel_launch(void* const* d_in, const int* in_sizes, int n_in,
                              void* d_out, int out_size)
{
    const float* x    = (const float*)d_in[0];
    const float* sre  = (const float*)d_in[1];
    const float* sim_ = (const float*)d_in[2];
    const float* Wdt  = (const float*)d_in[3];
    const float* bdt  = (const float*)d_in[4];
    const float* Wph  = (const float*)d_in[5];
    const float* bph  = (const float*)d_in[6];
    const float* WB   = (const float*)d_in[7];
    const float* WC   = (const float*)d_in[8];
    const float* Ar   = (const float*)d_in[9];
    const float* Ai   = (const float*)d_in[10];

    float* out = (float*)d_out;
    float* nre = out + (size_t)BATCH * DMODEL;
    float* nim = nre + (size_t)BATCH * RANK;

    const int smem1 = 64 * LDP * sizeof(float);          // 50176 B (>= stage 36864 B)
    const int smem2 = 2 * 128 * LDK2 * sizeof(float);    // 69632 B

    cudaFuncSetAttribute(proj_kernel, cudaFuncAttributeMaxDynamicSharedMemorySize, smem1);
    cudaFuncSetAttribute(out_kernel,  cudaFuncAttributeMaxDynamicSharedMemorySize, smem2);

    proj_kernel<<<BATCH / 64, 256, smem1>>>(x, sre, sim_, Wdt, bdt, Wph, bph, WB,
                                            Ar, Ai, nre, nim);
    out_kernel<<<dim3(BATCH / 128, DMODEL / 128), 256, smem2>>>(nre, WC, out);
}